// round 1
// baseline (speedup 1.0000x reference)
#include <cuda_runtime.h>

// Sparsemax over last axis: x [16, 2048, 1024] fp32 -> out same shape.
// 32768 independent rows of N=1024. One block per row, 256 threads,
// 4 values/thread held in registers (one float4 load / store per thread).
//
// Threshold tau found by Michelot's algorithm (exact fixed point of
// tau = (sum_{z>tau} z - 1) / count_{z>tau}), which equals the sort-based
// sparsemax threshold. Converges in a handful of iterations for gaussian
// rows; terminates exactly when fp32 tau stops changing (deterministic
// reduction order => bit-stable fixed point).

#define ROW_N    1024
#define THREADS  256
#define NWARP    (THREADS / 32)

__device__ __forceinline__ float warp_max(float v) {
#pragma unroll
    for (int o = 16; o; o >>= 1) v = fmaxf(v, __shfl_xor_sync(0xffffffffu, v, o));
    return v;
}

__device__ __forceinline__ float warp_sum(float v) {
#pragma unroll
    for (int o = 16; o; o >>= 1) v += __shfl_xor_sync(0xffffffffu, v, o);
    return v;
}

__global__ __launch_bounds__(THREADS, 8)
void sparsemax_kernel(const float* __restrict__ x, float* __restrict__ out) {
    __shared__ float s_a[NWARP];
    __shared__ float s_b[NWARP];

    const size_t row  = blockIdx.x;
    const int    tid  = threadIdx.x;
    const int    lane = tid & 31;
    const int    wid  = tid >> 5;

    const float4* __restrict__ xi =
        reinterpret_cast<const float4*>(x) + row * (ROW_N / 4) + tid;
    float4 v = *xi;

    // ---- row max (numerical-stability shift; matches reference) ----
    float m = fmaxf(fmaxf(v.x, v.y), fmaxf(v.z, v.w));
    m = warp_max(m);
    if (lane == 0) s_a[wid] = m;
    __syncthreads();
    m = s_a[0];
#pragma unroll
    for (int i = 1; i < NWARP; ++i) m = fmaxf(m, s_a[i]);

    v.x -= m; v.y -= m; v.z -= m; v.w -= m;
    __syncthreads();  // s_a reuse below

    // ---- initial tau = (sum(z) - 1) / N  (Michelot start: full support) ----
    float s = warp_sum(v.x + v.y + v.z + v.w);
    if (lane == 0) s_a[wid] = s;
    __syncthreads();
    float S = 0.f;
#pragma unroll
    for (int i = 0; i < NWARP; ++i) S += s_a[i];
    float tau = (S - 1.0f) * (1.0f / (float)ROW_N);
    __syncthreads();

    // ---- Michelot fixed-point iterations ----
    for (int it = 0; it < 64; ++it) {
        float ps = 0.f, pc = 0.f;
        if (v.x > tau) { ps += v.x; pc += 1.f; }
        if (v.y > tau) { ps += v.y; pc += 1.f; }
        if (v.z > tau) { ps += v.z; pc += 1.f; }
        if (v.w > tau) { ps += v.w; pc += 1.f; }
        ps = warp_sum(ps);
        pc = warp_sum(pc);
        if (lane == 0) { s_a[wid] = ps; s_b[wid] = pc; }
        __syncthreads();
        float Ssum = 0.f, Scnt = 0.f;
#pragma unroll
        for (int i = 0; i < NWARP; ++i) { Ssum += s_a[i]; Scnt += s_b[i]; }
        float ntau = (Ssum - 1.0f) / Scnt;  // Scnt >= 1 always (z_max=0 > tau<0)
        __syncthreads();  // protect s_a/s_b before next iteration's writes
        if (ntau == tau) break;             // uniform across block (same reduce order)
        tau = ntau;
    }

    // ---- project ----
    float4 o;
    o.x = fmaxf(v.x - tau, 0.0f);
    o.y = fmaxf(v.y - tau, 0.0f);
    o.z = fmaxf(v.z - tau, 0.0f);
    o.w = fmaxf(v.w - tau, 0.0f);
    reinterpret_cast<float4*>(out)[row * (ROW_N / 4) + tid] = o;
}

extern "C" void kernel_launch(void* const* d_in, const int* in_sizes, int n_in,
                              void* d_out, int out_size) {
    const float* x = (const float*)d_in[0];
    float* out = (float*)d_out;
    const int rows = in_sizes[0] / ROW_N;  // 32768
    sparsemax_kernel<<<rows, THREADS>>>(x, out);
}

// round 2
// speedup vs baseline: 4.1974x; 4.1974x over previous
#include <cuda_runtime.h>

// Sparsemax over last axis: x [16, 2048, 1024] fp32. 32768 rows of N=1024.
//
// One WARP per row: 32 threads x 32 values held in registers. All reductions
// are warp shuffles (no smem, no __syncthreads, warps converge independently).
//
// tau via Michelot's fixed point (exact sparsemax threshold), run UNSHIFTED:
// tau0 = (sum(x)-1)/N, iterate tau = (sum_{x>tau} x - 1)/count_{x>tau}.
// tau ascends monotonically to tau* < max(x), so count >= 1 always.

#define ROW_N   1024
#define VPT     32            // values per thread
#define WPB     8             // warps (rows) per block
#define THREADS (WPB * 32)

__device__ __forceinline__ float warp_sum(float v) {
#pragma unroll
    for (int o = 16; o; o >>= 1) v += __shfl_xor_sync(0xffffffffu, v, o);
    return v;
}

__global__ __launch_bounds__(THREADS)
void sparsemax_kernel(const float* __restrict__ x, float* __restrict__ out) {
    const int lane = threadIdx.x & 31;
    const int wid  = threadIdx.x >> 5;
    const size_t row = (size_t)blockIdx.x * WPB + wid;

    const float4* __restrict__ xr =
        reinterpret_cast<const float4*>(x) + row * (ROW_N / 4);

    float va[VPT];
    float s = 0.f;
#pragma unroll
    for (int k = 0; k < VPT / 4; ++k) {
        float4 f = xr[k * 32 + lane];       // coalesced: 32 lanes x 16B
        va[4 * k + 0] = f.x;
        va[4 * k + 1] = f.y;
        va[4 * k + 2] = f.z;
        va[4 * k + 3] = f.w;
        s += (f.x + f.y) + (f.z + f.w);
    }

    // initial tau: full support
    s = warp_sum(s);
    float tau = (s - 1.0f) * (1.0f / (float)ROW_N);

    // Michelot iterations (warp-independent, exact fp32 fixed point)
#pragma unroll 1
    for (int it = 0; it < 32; ++it) {
        float ps = 0.f, pc = 0.f;
#pragma unroll
        for (int i = 0; i < VPT; ++i) {
            if (va[i] > tau) { ps += va[i]; pc += 1.f; }
        }
        // reduce sum and count (two butterflies, 10 shfl total)
        ps = warp_sum(ps);
        pc = warp_sum(pc);
        float ntau = (ps - 1.0f) / pc;
        if (ntau == tau) break;   // warp-uniform: same reduce order on all lanes
        tau = ntau;
    }

    float4* __restrict__ orow =
        reinterpret_cast<float4*>(out) + row * (ROW_N / 4);
#pragma unroll
    for (int k = 0; k < VPT / 4; ++k) {
        float4 o;
        o.x = fmaxf(va[4 * k + 0] - tau, 0.0f);
        o.y = fmaxf(va[4 * k + 1] - tau, 0.0f);
        o.z = fmaxf(va[4 * k + 2] - tau, 0.0f);
        o.w = fmaxf(va[4 * k + 3] - tau, 0.0f);
        orow[k * 32 + lane] = o;
    }
}

extern "C" void kernel_launch(void* const* d_in, const int* in_sizes, int n_in,
                              void* d_out, int out_size) {
    const float* x = (const float*)d_in[0];
    float* out = (float*)d_out;
    const int rows = in_sizes[0] / ROW_N;   // 32768
    sparsemax_kernel<<<rows / WPB, THREADS>>>(x, out);
}

// round 3
// speedup vs baseline: 4.3612x; 1.0390x over previous
#include <cuda_runtime.h>

// Sparsemax over last axis: x [16, 2048, 1024] fp32. 32768 rows of N=1024.
//
// One WARP per row: 32 threads x 32 values in registers; reductions are pure
// shuffle butterflies (no smem, no block syncs).
//
// Threshold tau* solves sum_i max(x_i - tau, 0) = 1. Fixed-point iteration
// tau <- (sum_{x>tau} x - 1) / count_{x>tau}, started at tau0 = max(x) - 1.
// Since tau* >= max(x) - 1 always ({x > max-1} is a superset of the true
// support), iterates ascend monotonically to the exact fp32 fixed point in
// a handful of steps (starting support ~14 elements instead of ~512 when
// starting from the full-set mean). count >= 1 at every step because
// max(x) > tau for all iterates (tau <= max - 1/|S| < max).

#define ROW_N   1024
#define VPT     32            // values per thread
#define WPB     8             // warps (rows) per block
#define THREADS (WPB * 32)

__device__ __forceinline__ float warp_sum(float v) {
#pragma unroll
    for (int o = 16; o; o >>= 1) v += __shfl_xor_sync(0xffffffffu, v, o);
    return v;
}

__device__ __forceinline__ float warp_max(float v) {
#pragma unroll
    for (int o = 16; o; o >>= 1) v = fmaxf(v, __shfl_xor_sync(0xffffffffu, v, o));
    return v;
}

__global__ __launch_bounds__(THREADS)
void sparsemax_kernel(const float* __restrict__ x, float* __restrict__ out) {
    const int lane = threadIdx.x & 31;
    const int wid  = threadIdx.x >> 5;
    const size_t row = (size_t)blockIdx.x * WPB + wid;

    const float4* __restrict__ xr =
        reinterpret_cast<const float4*>(x) + row * (ROW_N / 4);

    float va[VPT];
    float m = -3.402823466e+38f;
#pragma unroll
    for (int k = 0; k < VPT / 4; ++k) {
        float4 f = xr[k * 32 + lane];       // coalesced: 32 lanes x 16B
        va[4 * k + 0] = f.x;
        va[4 * k + 1] = f.y;
        va[4 * k + 2] = f.z;
        va[4 * k + 3] = f.w;
        m = fmaxf(m, fmaxf(fmaxf(f.x, f.y), fmaxf(f.z, f.w)));
    }

    // tight lower start: tau* >= max - 1
    m = warp_max(m);
    float tau = m - 1.0f;

    // fixed-point iterations (warp-independent, exact fp32 fixed point)
#pragma unroll 1
    for (int it = 0; it < 32; ++it) {
        float ps = 0.f, pc = 0.f;
#pragma unroll
        for (int i = 0; i < VPT; ++i) {
            if (va[i] > tau) { ps += va[i]; pc += 1.f; }
        }
        ps = warp_sum(ps);
        pc = warp_sum(pc);
        float ntau = (ps - 1.0f) / pc;
        if (ntau == tau) break;   // warp-uniform (identical reduce order)
        tau = ntau;
    }

    float4* __restrict__ orow =
        reinterpret_cast<float4*>(out) + row * (ROW_N / 4);
#pragma unroll
    for (int k = 0; k < VPT / 4; ++k) {
        float4 o;
        o.x = fmaxf(va[4 * k + 0] - tau, 0.0f);
        o.y = fmaxf(va[4 * k + 1] - tau, 0.0f);
        o.z = fmaxf(va[4 * k + 2] - tau, 0.0f);
        o.w = fmaxf(va[4 * k + 3] - tau, 0.0f);
        orow[k * 32 + lane] = o;
    }
}

extern "C" void kernel_launch(void* const* d_in, const int* in_sizes, int n_in,
                              void* d_out, int out_size) {
    const float* x = (const float*)d_in[0];
    float* out = (float*)d_out;
    const int rows = in_sizes[0] / ROW_N;   // 32768
    sparsemax_kernel<<<rows / WPB, THREADS>>>(x, out);
}